// round 4
// baseline (speedup 1.0000x reference)
#include <cuda_runtime.h>
#include <math.h>

#define BATCH 1024
#define OBS_DIM 256
#define HIDDEN_DIM 512
#define ACTION_DIM 18
#define ETA 0.01f
#define LAMBDA 0.95f

// One block per batch element: 32 warps, each warp owns 16 (b,h) rows.
// M row lives in registers (single-pass read+write, evict-first), hidden lands
// in smem, and the q-head runs as an epilogue in the same block -> no second
// kernel, no global fences, no atomics.
__global__ __launch_bounds__(1024, 1) void mpn_fused_kernel(
    const float* __restrict__ obs,
    const float* __restrict__ M,
    const float* __restrict__ W,
    const float* __restrict__ b_h,
    const float* __restrict__ Wq,
    const float* __restrict__ bq,
    float* __restrict__ q,
    float* __restrict__ newM)
{
    const int b    = blockIdx.x;
    const int warp = threadIdx.x >> 5;
    const int lane = threadIdx.x & 31;

    __shared__ float4 s_obs[64];                      // obs[b, :]  (1 KB)
    __shared__ __align__(16) float s_hid[HIDDEN_DIM]; // hidden[b, :] (2 KB)

    if (threadIdx.x < 64)
        s_obs[threadIdx.x] = reinterpret_cast<const float4*>(obs + (size_t)b * OBS_DIM)[threadIdx.x];
    __syncthreads();

    const float4 o0 = s_obs[lane];
    const float4 o1 = s_obs[lane + 32];

    const float* Mbase = M    + (size_t)b * HIDDEN_DIM * OBS_DIM;
    float*       Nbase = newM + (size_t)b * HIDDEN_DIM * OBS_DIM;

    // software pipeline: preload M row for i=0
    int h = warp;
    const float4* Mrow = reinterpret_cast<const float4*>(Mbase + (size_t)h * OBS_DIM);
    float4 m0 = __ldcs(Mrow + lane);
    float4 m1 = __ldcs(Mrow + lane + 32);

    for (int i = 0; i < 16; i++) {
        // prefetch next row's M while this row computes
        float4 p0, p1;
        const int hn = h + 32;
        if (i < 15) {
            const float4* Mn = reinterpret_cast<const float4*>(Mbase + (size_t)hn * OBS_DIM);
            p0 = __ldcs(Mn + lane);
            p1 = __ldcs(Mn + lane + 32);
        }

        const float4* Wrow = reinterpret_cast<const float4*>(W + (size_t)h * OBS_DIM);
        const float4 w0 = Wrow[lane];
        const float4 w1 = Wrow[lane + 32];

        // acc = sum_o W*(1+M)*obs   (== base + plastic)
        float acc;
        acc  = w0.x * (1.0f + m0.x) * o0.x;
        acc += w0.y * (1.0f + m0.y) * o0.y;
        acc += w0.z * (1.0f + m0.z) * o0.z;
        acc += w0.w * (1.0f + m0.w) * o0.w;
        acc += w1.x * (1.0f + m1.x) * o1.x;
        acc += w1.y * (1.0f + m1.y) * o1.y;
        acc += w1.z * (1.0f + m1.z) * o1.z;
        acc += w1.w * (1.0f + m1.w) * o1.w;

        #pragma unroll
        for (int off = 16; off > 0; off >>= 1)
            acc += __shfl_xor_sync(0xffffffffu, acc, off);

        const float hval = tanhf(acc + __ldg(&b_h[h]));

        // Hebbian update from registers; single-use stream -> evict-first
        const float eh = ETA * hval;
        float4 n0, n1;
        n0.x = LAMBDA * m0.x + eh * o0.x;
        n0.y = LAMBDA * m0.y + eh * o0.y;
        n0.z = LAMBDA * m0.z + eh * o0.z;
        n0.w = LAMBDA * m0.w + eh * o0.w;
        n1.x = LAMBDA * m1.x + eh * o1.x;
        n1.y = LAMBDA * m1.y + eh * o1.y;
        n1.z = LAMBDA * m1.z + eh * o1.z;
        n1.w = LAMBDA * m1.w + eh * o1.w;
        float4* Nrow = reinterpret_cast<float4*>(Nbase + (size_t)h * OBS_DIM);
        __stcs(Nrow + lane,      n0);
        __stcs(Nrow + lane + 32, n1);

        if (lane == 0)
            s_hid[h] = hval;

        m0 = p0; m1 = p1; h = hn;
    }

    // ---- q-head epilogue: q[b,a] = dot(hidden, Wq[a]) + bq[a] ----
    __syncthreads();
    if (warp < ACTION_DIM) {
        const int a = warp;
        const float4* hid4 = reinterpret_cast<const float4*>(s_hid);
        const float4* wq   = reinterpret_cast<const float4*>(Wq + (size_t)a * HIDDEN_DIM);
        float accq = 0.0f;
        #pragma unroll
        for (int i = 0; i < 4; i++) {
            float4 hv = hid4[lane + 32 * i];
            float4 wv = wq[lane + 32 * i];
            accq += hv.x * wv.x + hv.y * wv.y + hv.z * wv.z + hv.w * wv.w;
        }
        #pragma unroll
        for (int off = 16; off > 0; off >>= 1)
            accq += __shfl_xor_sync(0xffffffffu, accq, off);
        if (lane == 0)
            q[(size_t)b * ACTION_DIM + a] = accq + __ldg(&bq[a]);
    }
}

extern "C" void kernel_launch(void* const* d_in, const int* in_sizes, int n_in,
                              void* d_out, int out_size)
{
    const float* obs = (const float*)d_in[0];   // [B, O]
    const float* M   = (const float*)d_in[1];   // [B, H, O]
    const float* W   = (const float*)d_in[2];   // [H, O]
    const float* b_h = (const float*)d_in[3];   // [H]
    const float* Wq  = (const float*)d_in[4];   // [A, H]
    const float* bq  = (const float*)d_in[5];   // [A]

    float* out  = (float*)d_out;
    float* q    = out;                              // [B, A]
    float* newM = out + (size_t)BATCH * ACTION_DIM; // [B, H, O]

    mpn_fused_kernel<<<BATCH, 1024>>>(obs, M, W, b_h, Wq, bq, q, newM);
}

// round 5
// speedup vs baseline: 1.0536x; 1.0536x over previous
#include <cuda_runtime.h>
#include <math.h>

#define BATCH 1024
#define OBS_DIM 256
#define HIDDEN_DIM 512
#define ACTION_DIM 18
#define ETA 0.01f
#define LAMBDA 0.95f

// scratch for hidden activations (allocation-free rule: static __device__ array)
__device__ float g_hidden[BATCH * HIDDEN_DIM];

// One warp per (b, h) row; 8 warps/block share one batch's obs in smem.
// M row (256 f32) lives entirely in registers: single-pass read + single-pass write.
__global__ __launch_bounds__(256, 8) void mpn_main_kernel(
    const float* __restrict__ obs,
    const float* __restrict__ M,
    const float* __restrict__ W,
    const float* __restrict__ b_h,
    float* __restrict__ newM)
{
    const int b    = blockIdx.x >> 6;        // 64 h-groups per batch (512/8)
    const int hg   = blockIdx.x & 63;
    const int warp = threadIdx.x >> 5;
    const int lane = threadIdx.x & 31;
    const int h    = hg * 8 + warp;

    __shared__ float4 s_obs[64];             // 256 floats = 1 KB
    if (threadIdx.x < 64)
        s_obs[threadIdx.x] = reinterpret_cast<const float4*>(obs + b * OBS_DIM)[threadIdx.x];
    __syncthreads();

    const size_t row = ((size_t)b * HIDDEN_DIM + h) * OBS_DIM;
    const float4* Mrow = reinterpret_cast<const float4*>(M + row);
    const float4* Wrow = reinterpret_cast<const float4*>(W + (size_t)h * OBS_DIM);
    float4* Nrow = reinterpret_cast<float4*>(newM + row);

    // coalesced: lanes cover float4[0..31] and float4[32..63] of the row.
    // M is read exactly once -> evict-first.
    float4 m0 = __ldcs(Mrow + lane);
    float4 m1 = __ldcs(Mrow + lane + 32);
    float4 w0 = Wrow[lane];
    float4 w1 = Wrow[lane + 32];
    float4 o0 = s_obs[lane];
    float4 o1 = s_obs[lane + 32];

    // acc = sum_o W*(1+M)*obs   (== base + plastic)
    float acc;
    acc  = w0.x * (1.0f + m0.x) * o0.x;
    acc += w0.y * (1.0f + m0.y) * o0.y;
    acc += w0.z * (1.0f + m0.z) * o0.z;
    acc += w0.w * (1.0f + m0.w) * o0.w;
    acc += w1.x * (1.0f + m1.x) * o1.x;
    acc += w1.y * (1.0f + m1.y) * o1.y;
    acc += w1.z * (1.0f + m1.z) * o1.z;
    acc += w1.w * (1.0f + m1.w) * o1.w;

    #pragma unroll
    for (int off = 16; off > 0; off >>= 1)
        acc += __shfl_xor_sync(0xffffffffu, acc, off);

    const float hval = tanhf(acc + __ldg(&b_h[h]));   // same value in all lanes

    // Hebbian update written from registers already in hand; never re-read -> evict-first.
    const float eh = ETA * hval;
    float4 n0, n1;
    n0.x = LAMBDA * m0.x + eh * o0.x;
    n0.y = LAMBDA * m0.y + eh * o0.y;
    n0.z = LAMBDA * m0.z + eh * o0.z;
    n0.w = LAMBDA * m0.w + eh * o0.w;
    n1.x = LAMBDA * m1.x + eh * o1.x;
    n1.y = LAMBDA * m1.y + eh * o1.y;
    n1.z = LAMBDA * m1.z + eh * o1.z;
    n1.w = LAMBDA * m1.w + eh * o1.w;
    __stcs(Nrow + lane,      n0);
    __stcs(Nrow + lane + 32, n1);

    if (lane == 0)
        g_hidden[b * HIDDEN_DIM + h] = hval;
}

// q[b,a] = sum_h hidden[b,h] * Wq[a,h] + bq[a]
// 64 blocks x 512 threads. Wq (36 KB) staged ONCE per block in smem;
// one warp per batch element (16 batches/block), hidden row in registers.
__global__ __launch_bounds__(512) void q_head_kernel(
    const float* __restrict__ Wq,
    const float* __restrict__ bq,
    float* __restrict__ q)
{
    const int warp = threadIdx.x >> 5;   // 0..15
    const int lane = threadIdx.x & 31;

    __shared__ __align__(16) float s_wq[ACTION_DIM * HIDDEN_DIM]; // 36 KB
    {
        const float4* src = reinterpret_cast<const float4*>(Wq);
        float4* dst = reinterpret_cast<float4*>(s_wq);
        for (int i = threadIdx.x; i < ACTION_DIM * HIDDEN_DIM / 4; i += 512)
            dst[i] = src[i];
    }
    __syncthreads();

    const int b = blockIdx.x * 16 + warp;

    // hidden[b, :] -> 16 floats per lane (4 coalesced float4 loads)
    const float4* hid4 = reinterpret_cast<const float4*>(g_hidden + (size_t)b * HIDDEN_DIM);
    float4 hv[4];
    #pragma unroll
    for (int i = 0; i < 4; i++)
        hv[i] = hid4[lane + 32 * i];

    float accq[ACTION_DIM];
    #pragma unroll
    for (int a = 0; a < ACTION_DIM; a++) {
        const float4* wq = reinterpret_cast<const float4*>(s_wq + a * HIDDEN_DIM);
        float acc = 0.0f;
        #pragma unroll
        for (int i = 0; i < 4; i++) {
            float4 wv = wq[lane + 32 * i];
            acc += hv[i].x * wv.x + hv[i].y * wv.y + hv[i].z * wv.z + hv[i].w * wv.w;
        }
        accq[a] = acc;
    }

    #pragma unroll
    for (int a = 0; a < ACTION_DIM; a++) {
        #pragma unroll
        for (int off = 16; off > 0; off >>= 1)
            accq[a] += __shfl_xor_sync(0xffffffffu, accq[a], off);
    }

    if (lane == 0) {
        #pragma unroll
        for (int a = 0; a < ACTION_DIM; a++)
            q[(size_t)b * ACTION_DIM + a] = accq[a] + __ldg(&bq[a]);
    }
}

extern "C" void kernel_launch(void* const* d_in, const int* in_sizes, int n_in,
                              void* d_out, int out_size)
{
    const float* obs = (const float*)d_in[0];   // [B, O]
    const float* M   = (const float*)d_in[1];   // [B, H, O]
    const float* W   = (const float*)d_in[2];   // [H, O]
    const float* b_h = (const float*)d_in[3];   // [H]
    const float* Wq  = (const float*)d_in[4];   // [A, H]
    const float* bq  = (const float*)d_in[5];   // [A]

    float* out  = (float*)d_out;
    float* q    = out;                              // [B, A]
    float* newM = out + (size_t)BATCH * ACTION_DIM; // [B, H, O]

    mpn_main_kernel<<<BATCH * (HIDDEN_DIM / 8), 256>>>(obs, M, W, b_h, newM);
    q_head_kernel<<<BATCH / 16, 512>>>(Wq, bq, q);
}